// round 4
// baseline (speedup 1.0000x reference)
#include <cuda_runtime.h>
#include <cstdint>

#define NDIM    128
#define EDIM    64
#define KDIM    192
#define BM      128
#define THREADS 128

// padded smem strides (floats) — conflict-free fragment access
// A frag lanes: (g*AS + t) mod 32, AS%32=4  -> bijective over g(0..7),t(0..3)
// B frag lanes: (t*WS + g) mod 32, WS%32=8  -> bijective
#define AS_STRIDE 196
#define WS_STRIDE 136

#define SMEM_FLOATS (KDIM * WS_STRIDE + BM * AS_STRIDE + NDIM)
#define SMEM_BYTES  (SMEM_FLOATS * sizeof(float))

__device__ int g_idx_is64;
__global__ void detect_idx_dtype_kernel(const int* __restrict__ buf, int n_words) {
    int nz = 0;
    for (int i = 1; i < n_words; i += 2) nz += (buf[i] != 0);
    g_idx_is64 = (nz == 0) ? 1 : 0;
}

__device__ __forceinline__ uint32_t f32_to_tf32(float x) {
    uint32_t r;
    asm volatile("cvt.rna.tf32.f32 %0, %1;" : "=r"(r) : "f"(x));
    return r;
}

__device__ __forceinline__ void mma_tf32(float d[4], const uint32_t a[4], const uint32_t b[2]) {
    asm volatile(
        "mma.sync.aligned.m16n8k8.row.col.f32.tf32.tf32.f32 "
        "{%0,%1,%2,%3}, {%4,%5,%6,%7}, {%8,%9}, {%0,%1,%2,%3};\n"
        : "+f"(d[0]), "+f"(d[1]), "+f"(d[2]), "+f"(d[3])
        : "r"(a[0]), "r"(a[1]), "r"(a[2]), "r"(a[3]),
          "r"(b[0]), "r"(b[1]));
}

__device__ __forceinline__ void load_a_frag(uint32_t a[4][4], const float* __restrict__ Abase,
                                            int k0) {
    #pragma unroll
    for (int i = 0; i < 4; i++) {
        const float* Ar = Abase + i * 16 * AS_STRIDE + k0;
        a[i][0] = __float_as_uint(Ar[0]);
        a[i][1] = __float_as_uint(Ar[8 * AS_STRIDE]);
        a[i][2] = __float_as_uint(Ar[4]);
        a[i][3] = __float_as_uint(Ar[8 * AS_STRIDE + 4]);
    }
}
__device__ __forceinline__ void load_b_frag(uint32_t b[8][2], const float* __restrict__ Wbase,
                                            int k0) {
    #pragma unroll
    for (int j = 0; j < 8; j++) {
        const float* Wr = Wbase + k0 * WS_STRIDE + j * 8;
        b[j][0] = __float_as_uint(Wr[0]);
        b[j][1] = __float_as_uint(Wr[4 * WS_STRIDE]);
    }
}

__global__ void __launch_bounds__(THREADS, 1)
atom2bond_kernel(const float* __restrict__ atom,
                 const float* __restrict__ edge,
                 const void*  __restrict__ src_idx,
                 const float* __restrict__ Wg,
                 const float* __restrict__ bg,
                 float* __restrict__ out,
                 int E, int ntiles, long n_nodes) {
    extern __shared__ float smem[];
    float* Ws = smem;                          // [KDIM][WS_STRIDE]
    float* As = Ws + KDIM * WS_STRIDE;         // [BM][AS_STRIDE]
    float* Bs = As + BM * AS_STRIDE;           // [NDIM] bias

    const int tid  = threadIdx.x;
    const int lane = tid & 31;
    const int warp = tid >> 5;                 // 0..3
    const int g = lane >> 2;
    const int t = lane & 3;
    const int wm = warp >> 1;                  // row half (64 edges)
    const int wn = warp & 1;                   // col half (64 outputs)
    const int is64 = g_idx_is64;

    // gather decomposition: 4 threads per row
    const int rq = tid >> 2;                   // 0..31 row-within-block
    const int q  = tid & 3;                    // column quarter (12 float4 each)

    // ---- load W (tf32) + bias once ----
    {
        const int F4 = NDIM / 4;
        for (int v = tid; v < KDIM * F4; v += THREADS) {
            int row = v / F4;
            int c4  = (v % F4) * 4;
            float4 w = *(const float4*)(Wg + (long)row * NDIM + c4);
            float* dst = Ws + row * WS_STRIDE + c4;
            dst[0] = __uint_as_float(f32_to_tf32(w.x));
            dst[1] = __uint_as_float(f32_to_tf32(w.y));
            dst[2] = __uint_as_float(f32_to_tf32(w.z));
            dst[3] = __uint_as_float(f32_to_tf32(w.w));
        }
        if (tid < NDIM) Bs[tid] = bg[tid];
    }

    const float* Abase = As + (wm * 64 + g) * AS_STRIDE + t;   // fragment base
    const float* Wbase = Ws + t * WS_STRIDE + wn * 64 + g;

    for (int tile = blockIdx.x; tile < ntiles; tile += gridDim.x) {
        const long eb = (long)tile * BM;

        __syncthreads();   // all warps done reading As from previous tile

        // ---- gather + concat tile (tf32, padded layout) ----
        {
            const float* arow[4];
            const float* erow[4];
            bool valid[4];
            #pragma unroll
            for (int blk = 0; blk < 4; blk++) {
                const int  r = blk * 32 + rq;
                const long e = eb + r;
                valid[blk] = (e < (long)E);
                long s = 0;
                if (valid[blk]) {
                    s = is64 ? (long)((const long long*)src_idx)[e]
                             : (long)((const int*)src_idx)[e];
                    if (s < 0) s = 0;
                    if (s >= n_nodes) s = n_nodes - 1;
                }
                arow[blk] = atom + s * (long)NDIM;
                erow[blk] = edge + e * (long)EDIM;
            }
            #pragma unroll
            for (int blk = 0; blk < 4; blk++) {
                float* dst = As + (blk * 32 + rq) * AS_STRIDE;
                #pragma unroll
                for (int u = 0; u < 12; u++) {
                    const int cf4 = q * 12 + u;   // float4 index in 192-float row
                    float4 v;
                    if (!valid[blk])     v = make_float4(0.f, 0.f, 0.f, 0.f);
                    else if (cf4 < 32)   v = *(const float4*)(arow[blk] + cf4 * 4);
                    else                 v = *(const float4*)(erow[blk] + (cf4 - 32) * 4);
                    uint4 u4;
                    u4.x = f32_to_tf32(v.x); u4.y = f32_to_tf32(v.y);
                    u4.z = f32_to_tf32(v.z); u4.w = f32_to_tf32(v.w);
                    *(uint4*)(dst + cf4 * 4) = u4;
                }
            }
        }
        __syncthreads();

        // ---- MMA mainloop: each warp 64 edges x 64 outputs, K=192 ----
        float acc[4][8][4];
        #pragma unroll
        for (int i = 0; i < 4; i++)
            #pragma unroll
            for (int j = 0; j < 8; j++)
                #pragma unroll
                for (int c = 0; c < 4; c++) acc[i][j][c] = 0.f;

        uint32_t a[2][4][4], b[2][8][2];
        load_a_frag(a[0], Abase, 0);
        load_b_frag(b[0], Wbase, 0);

        #pragma unroll
        for (int kk = 0; kk < KDIM / 8; kk++) {
            const int cur = kk & 1;
            const int nxt = cur ^ 1;
            if (kk < KDIM / 8 - 1) {
                load_a_frag(a[nxt], Abase, (kk + 1) * 8);
                load_b_frag(b[nxt], Wbase, (kk + 1) * 8);
            }
            #pragma unroll
            for (int i = 0; i < 4; i++)
                #pragma unroll
                for (int j = 0; j < 8; j++)
                    mma_tf32(acc[i][j], a[cur][i], b[cur][j]);
        }

        // ---- epilogue: bias + relu, float2 stores ----
        #pragma unroll
        for (int i = 0; i < 4; i++) {
            #pragma unroll
            for (int rr = 0; rr < 2; rr++) {
                const long e = eb + wm * 64 + i * 16 + rr * 8 + g;
                if (e < (long)E) {
                    float* orow = out + e * (long)NDIM;
                    #pragma unroll
                    for (int j = 0; j < 8; j++) {
                        const int c = wn * 64 + j * 8 + 2 * t;
                        float v0 = fmaxf(acc[i][j][rr * 2 + 0] + Bs[c], 0.f);
                        float v1 = fmaxf(acc[i][j][rr * 2 + 1] + Bs[c + 1], 0.f);
                        *(float2*)(orow + c) = make_float2(v0, v1);
                    }
                }
            }
        }
    }
}

extern "C" void kernel_launch(void* const* d_in, const int* in_sizes, int n_in,
                              void* d_out, int out_size) {
    const float* atom = (const float*)d_in[0];   // [N_NODES,128] f32
    const float* edge = (const float*)d_in[1];   // [E,64] f32
    const void*  src  = d_in[2];                 // [E] int32 or int64 (detected)
    const float* W    = (const float*)d_in[3];   // [192,128] f32
    const float* b    = (const float*)d_in[4];   // [128] f32
    float* out = (float*)d_out;                  // [E,128] f32

    const int  E       = in_sizes[2];
    const long n_nodes = (long)in_sizes[0] / NDIM;
    const int  ntiles  = (E + BM - 1) / BM;

    int n_words = E < 2048 ? E : 2048;
    detect_idx_dtype_kernel<<<1, 1>>>((const int*)src, n_words);

    cudaFuncSetAttribute(atom2bond_kernel,
                         cudaFuncAttributeMaxDynamicSharedMemorySize, SMEM_BYTES);

    int grid = ntiles < 148 ? ntiles : 148;
    atom2bond_kernel<<<grid, THREADS, SMEM_BYTES>>>(atom, edge, src, W, b, out,
                                                    E, ntiles, n_nodes);
}

// round 5
// speedup vs baseline: 1.6783x; 1.6783x over previous
#include <cuda_runtime.h>
#include <cstdint>

#define NDIM    128
#define EDIM    64
#define KDIM    192
#define BM      128
#define THREADS 256
#define NKK     24                      // K steps of 8

#define AS_STRIDE 196                   // (4g+t) mod 32 bijective -> conflict-free A frags
#define WF_FLOATS (2 * NKK * 8 * 2 * 32)        // 24576 floats, fragment-order W
#define SMEM_FLOATS (WF_FLOATS + BM * AS_STRIDE + NDIM)
#define SMEM_BYTES  (SMEM_FLOATS * sizeof(float))

__device__ int g_idx_is64;
__global__ void detect_idx_dtype_kernel(const int* __restrict__ buf, int n_words) {
    int nz = 0;
    for (int i = 1; i < n_words; i += 2) nz += (buf[i] != 0);
    g_idx_is64 = (nz == 0) ? 1 : 0;
}

__device__ __forceinline__ uint32_t f32_to_tf32(float x) {
    uint32_t r;
    asm volatile("cvt.rna.tf32.f32 %0, %1;" : "=r"(r) : "f"(x));
    return r;
}

__device__ __forceinline__ void mma_tf32(float d[4], const uint32_t a[4], const uint32_t b[2]) {
    asm volatile(
        "mma.sync.aligned.m16n8k8.row.col.f32.tf32.tf32.f32 "
        "{%0,%1,%2,%3}, {%4,%5,%6,%7}, {%8,%9}, {%0,%1,%2,%3};\n"
        : "+f"(d[0]), "+f"(d[1]), "+f"(d[2]), "+f"(d[3])
        : "r"(a[0]), "r"(a[1]), "r"(a[2]), "r"(a[3]),
          "r"(b[0]), "r"(b[1]));
}

// ---- gather stage: LDG next tile into registers (issued early, overlaps MMA) ----
__device__ __forceinline__ void gather_ldg(float4 st[24], long eb,
                                           const float* __restrict__ atom,
                                           const float* __restrict__ edge,
                                           const void* __restrict__ src_idx,
                                           int is64, int E, long n_nodes) {
    const int tid  = threadIdx.x;
    const int r    = tid >> 1;
    const int half = tid & 1;
    const long e   = eb + r;
    const bool valid = (e < (long)E);
    long s = 0;
    if (valid) {
        s = is64 ? (long)((const long long*)src_idx)[e]
                 : (long)((const int*)src_idx)[e];
        if (s < 0) s = 0;
        if (s >= n_nodes) s = n_nodes - 1;
    }
    const float* arow = atom + s * (long)NDIM;
    const float* erow = edge + e * (long)EDIM;
    #pragma unroll
    for (int u = 0; u < 24; u++) {
        const int cf4 = half * 24 + u;
        if (!valid)        st[u] = make_float4(0.f, 0.f, 0.f, 0.f);
        else if (cf4 < 32) st[u] = __ldg((const float4*)(arow + cf4 * 4));
        else               st[u] = __ldg((const float4*)(erow + (cf4 - 32) * 4));
    }
}

__device__ __forceinline__ void sts_stage(const float4 st[24], float* __restrict__ As) {
    const int tid  = threadIdx.x;
    const int r    = tid >> 1;
    const int half = tid & 1;
    float* dst = As + r * AS_STRIDE;
    #pragma unroll
    for (int u = 0; u < 24; u++) {
        const int cf4 = half * 24 + u;
        uint4 u4;
        u4.x = f32_to_tf32(st[u].x); u4.y = f32_to_tf32(st[u].y);
        u4.z = f32_to_tf32(st[u].z); u4.w = f32_to_tf32(st[u].w);
        *(uint4*)(dst + cf4 * 4) = u4;
    }
}

__global__ void __launch_bounds__(THREADS, 1)
atom2bond_kernel(const float* __restrict__ atom,
                 const float* __restrict__ edge,
                 const void*  __restrict__ src_idx,
                 const float* __restrict__ Wg,
                 const float* __restrict__ bg,
                 float* __restrict__ out,
                 int E, int ntiles, long n_nodes) {
    extern __shared__ float smem[];
    float* Wf = smem;                          // fragment-order W, 24576 f
    float* As = Wf + WF_FLOATS;                // [BM][AS_STRIDE]
    float* Bs = As + BM * AS_STRIDE;           // bias [128]

    const int tid  = threadIdx.x;
    const int lane = tid & 31;
    const int warp = tid >> 5;                 // 0..7
    const int g  = lane >> 2;
    const int tg = lane & 3;
    const int wm = warp >> 1;                  // 0..3 : 32-edge block
    const int wn = warp & 1;                   // 0..1 : 64-col half
    const int is64 = g_idx_is64;

    // ---- build fragment-order W + bias (once) ----
    // Wf[((wn*NKK + kk)*8 + j)*2 + h][lane] = tf32(W[kk*8 + tg + 4h][wn*64 + j*8 + g])
    for (int idx = tid; idx < WF_FLOATS; idx += THREADS) {
        const int l    = idx & 31;
        const int h    = (idx >> 5) & 1;
        const int j    = (idx >> 6) & 7;
        const int rest = idx >> 9;
        const int kk   = rest % NKK;
        const int wnn  = rest / NKK;
        const int k = kk * 8 + (l & 3) + h * 4;
        const int n = wnn * 64 + j * 8 + (l >> 2);
        Wf[idx] = __uint_as_float(f32_to_tf32(Wg[k * NDIM + n]));
    }
    if (tid < NDIM) Bs[tid] = bg[tid];

    const float* Abase = As + (wm * 32 + g) * AS_STRIDE + tg;
    const float* Wbase = Wf + wn * (NKK * 512) + lane;

    // ---- prologue: gather + store tile 0 ----
    long tile = blockIdx.x;
    float4 st[24];
    gather_ldg(st, tile * (long)BM, atom, edge, src_idx, is64, E, n_nodes);
    sts_stage(st, As);
    __syncthreads();

    // ---- pipelined persistent loop ----
    for (;;) {
        const long tn = tile + gridDim.x;
        const bool more = (tn < (long)ntiles);

        // issue LDGs for next tile NOW — latency hidden under MMA below
        if (more)
            gather_ldg(st, tn * (long)BM, atom, edge, src_idx, is64, E, n_nodes);

        // ---- MMA: warp computes 32 edges x 64 cols, K=192 ----
        float acc[2][8][4];
        #pragma unroll
        for (int i = 0; i < 2; i++)
            #pragma unroll
            for (int j = 0; j < 8; j++)
                #pragma unroll
                for (int c = 0; c < 4; c++) acc[i][j][c] = 0.f;

        #pragma unroll
        for (int kk = 0; kk < NKK; kk++) {
            uint32_t a[2][4];
            #pragma unroll
            for (int i = 0; i < 2; i++) {
                const float* Ar = Abase + i * 16 * AS_STRIDE + kk * 8;
                a[i][0] = __float_as_uint(Ar[0]);
                a[i][1] = __float_as_uint(Ar[8 * AS_STRIDE]);
                a[i][2] = __float_as_uint(Ar[4]);
                a[i][3] = __float_as_uint(Ar[8 * AS_STRIDE + 4]);
            }
            uint32_t b[8][2];
            const float* Wr = Wbase + kk * 512;
            #pragma unroll
            for (int j = 0; j < 8; j++) {
                b[j][0] = __float_as_uint(Wr[(j * 2 + 0) * 32]);
                b[j][1] = __float_as_uint(Wr[(j * 2 + 1) * 32]);
            }
            #pragma unroll
            for (int i = 0; i < 2; i++)
                #pragma unroll
                for (int j = 0; j < 8; j++)
                    mma_tf32(acc[i][j], a[i], b[j]);
        }

        // ---- epilogue (register-resident, before barrier) ----
        const long eb = tile * (long)BM;
        #pragma unroll
        for (int i = 0; i < 2; i++) {
            #pragma unroll
            for (int rr = 0; rr < 2; rr++) {
                const long e = eb + wm * 32 + i * 16 + rr * 8 + g;
                if (e < (long)E) {
                    float* orow = out + e * (long)NDIM;
                    #pragma unroll
                    for (int j = 0; j < 8; j++) {
                        const int c = wn * 64 + j * 8 + 2 * tg;
                        float v0 = fmaxf(acc[i][j][rr * 2 + 0] + Bs[c], 0.f);
                        float v1 = fmaxf(acc[i][j][rr * 2 + 1] + Bs[c + 1], 0.f);
                        *(float2*)(orow + c) = make_float2(v0, v1);
                    }
                }
            }
        }

        if (!more) break;
        __syncthreads();          // everyone done reading As(tile)
        sts_stage(st, As);        // stage regs (arrived during MMA) -> smem
        __syncthreads();
        tile = tn;
    }
}

extern "C" void kernel_launch(void* const* d_in, const int* in_sizes, int n_in,
                              void* d_out, int out_size) {
    const float* atom = (const float*)d_in[0];   // [N_NODES,128] f32
    const float* edge = (const float*)d_in[1];   // [E,64] f32
    const void*  src  = d_in[2];                 // [E] int32 or int64 (detected)
    const float* W    = (const float*)d_in[3];   // [192,128] f32
    const float* b    = (const float*)d_in[4];   // [128] f32
    float* out = (float*)d_out;                  // [E,128] f32

    const int  E       = in_sizes[2];
    const long n_nodes = (long)in_sizes[0] / NDIM;
    const int  ntiles  = (E + BM - 1) / BM;

    int n_words = E < 2048 ? E : 2048;
    detect_idx_dtype_kernel<<<1, 1>>>((const int*)src, n_words);

    cudaFuncSetAttribute(atom2bond_kernel,
                         cudaFuncAttributeMaxDynamicSharedMemorySize, SMEM_BYTES);

    int grid = ntiles < 148 ? ntiles : 148;
    atom2bond_kernel<<<grid, THREADS, SMEM_BYTES>>>(atom, edge, src, W, b, out,
                                                    E, ntiles, n_nodes);
}

// round 6
// speedup vs baseline: 2.3597x; 1.4060x over previous
#include <cuda_runtime.h>
#include <cstdint>

#define NDIM    128
#define EDIM    64
#define KDIM    192
#define BM      128
#define THREADS 256
#define NKK     24
#define AS_STRIDE 196                       // (4g+t) mod 32 bijective; 16B-mult row stride (784B)

#define WF_WORDS (2 * NKK * 32 * 20)        // 30720 words, per-lane-contiguous W frags
#define OFF_MBAR 0
#define OFF_WF   1024
#define OFF_AS   (OFF_WF + WF_WORDS * 4)    // 123904 (16B aligned)
#define SMEM_TOTAL (OFF_AS + BM * AS_STRIDE * 4)   // 224256 B

#define ATOM_CAP_ROWS 16384
__device__ float g_atom_r[ATOM_CAP_ROWS * NDIM];   // tf32-pre-rounded atom table
__device__ int   g_idx_is64;

__global__ void detect_idx_dtype_kernel(const int* __restrict__ buf, int n_words) {
    int nz = 0;
    for (int i = 1; i < n_words; i += 2) nz += (buf[i] != 0);
    g_idx_is64 = (nz == 0) ? 1 : 0;
}

__device__ __forceinline__ uint32_t f32_to_tf32(float x) {
    uint32_t r;
    asm volatile("cvt.rna.tf32.f32 %0, %1;" : "=r"(r) : "f"(x));
    return r;
}

__global__ void round_atom_kernel(const float* __restrict__ a, long n) {
    for (long i = blockIdx.x * (long)blockDim.x + threadIdx.x; i < n;
         i += (long)gridDim.x * blockDim.x)
        g_atom_r[i] = __uint_as_float(f32_to_tf32(a[i]));
}

__device__ __forceinline__ void mma_tf32(float d[4], const uint32_t a[4], const uint32_t b[2]) {
    asm volatile(
        "mma.sync.aligned.m16n8k8.row.col.f32.tf32.tf32.f32 "
        "{%0,%1,%2,%3}, {%4,%5,%6,%7}, {%8,%9}, {%0,%1,%2,%3};\n"
        : "+f"(d[0]), "+f"(d[1]), "+f"(d[2]), "+f"(d[3])
        : "r"(a[0]), "r"(a[1]), "r"(a[2]), "r"(a[3]),
          "r"(b[0]), "r"(b[1]));
}

__device__ __forceinline__ uint32_t smem_u32(const void* p) {
    uint32_t a;
    asm("{ .reg .u64 t; cvta.to.shared.u64 t, %1; cvt.u32.u64 %0, t; }" : "=r"(a) : "l"(p));
    return a;
}

#define MBAR_INIT(mb, c) \
    asm volatile("mbarrier.init.shared.b64 [%0], %1;" :: "r"(mb), "r"((uint32_t)(c)) : "memory")
#define MBAR_ARRIVE(mb) \
    asm volatile("mbarrier.arrive.shared::cta.b64 _, [%0];" :: "r"(mb) : "memory")
#define MBAR_ARRIVE_TX(mb, tx) \
    asm volatile("mbarrier.arrive.expect_tx.shared::cta.b64 _, [%0], %1;" \
                 :: "r"(mb), "r"((uint32_t)(tx)) : "memory")
#define MBAR_WAIT(mb, ph) do { \
    asm volatile("{\n\t.reg .pred P1;\n\t" \
        "WL_%=:\n\t" \
        "mbarrier.try_wait.parity.acquire.cta.shared::cta.b64 P1, [%0], %1, 0x989680;\n\t" \
        "@P1 bra.uni WD_%=;\n\t" \
        "bra.uni WL_%=;\n\t" \
        "WD_%=:\n\t}" :: "r"(mb), "r"((uint32_t)(ph)) : "memory"); \
} while (0)
#define BULK_CP(dst, src, bytes, mb) \
    asm volatile("cp.async.bulk.shared::cta.global.mbarrier::complete_tx::bytes [%0], [%1], %2, [%3];" \
                 :: "r"(dst), "l"(src), "r"((uint32_t)(bytes)), "r"(mb) : "memory")

// ---- edge LDG (coalesced float4 grid-stride over the contiguous 32KB tile slab) ----
__device__ __forceinline__ void edge_ldg(float4 ev[8], long tile,
                                         const float* __restrict__ edge, int E) {
    const int tid = threadIdx.x;
    const long eb = tile * (long)BM;
    const int vf4 = (int)((long)E - eb) * (EDIM / 4);     // valid float4 count (<= 2048)
    const float4* base = (const float4*)(edge + eb * EDIM);
    #pragma unroll
    for (int u = 0; u < 8; u++) {
        const int f4 = u * THREADS + tid;
        ev[u] = (f4 < vf4) ? __ldg(base + f4) : make_float4(0.f, 0.f, 0.f, 0.f);
    }
}
__device__ __forceinline__ void edge_sts(const float4 ev[8], float* __restrict__ As, int vf4) {
    const int tid = threadIdx.x;
    #pragma unroll
    for (int u = 0; u < 8; u++) {
        const int f4 = u * THREADS + tid;
        if (f4 < vf4) {
            const int r   = f4 >> 4;            // 16 float4 per 64-float edge row
            const int off = (f4 & 15) * 4;      // word offset within edge part
            uint4 q;
            q.x = f32_to_tf32(ev[u].x); q.y = f32_to_tf32(ev[u].y);
            q.z = f32_to_tf32(ev[u].z); q.w = f32_to_tf32(ev[u].w);
            *(uint4*)(As + r * AS_STRIDE + NDIM + off) = q;
        }
    }
}
// ---- atom rows via bulk copy; every thread arrives exactly once ----
__device__ __forceinline__ void atom_issue(uint32_t as_smem, uint32_t mbar, long tile,
                                           long s, const float* __restrict__ asrc, int E) {
    const int tid = threadIdx.x;
    if (tid < BM) {
        const long e = tile * (long)BM + tid;
        if (e < (long)E) {
            MBAR_ARRIVE_TX(mbar, NDIM * 4);
            BULK_CP(as_smem + (uint32_t)(tid * AS_STRIDE * 4),
                    asrc + s * (long)NDIM, NDIM * 4, mbar);
        } else {
            MBAR_ARRIVE(mbar);
        }
    } else {
        MBAR_ARRIVE(mbar);
    }
}
__device__ __forceinline__ long idx_ld(long tile, const void* __restrict__ src_idx,
                                       int is64, int E, long n_nodes) {
    const int tid = threadIdx.x;
    long s = 0;
    if (tid < BM) {
        const long e = tile * (long)BM + tid;
        if (e < (long)E) {
            s = is64 ? (long)((const long long*)src_idx)[e]
                     : (long)((const int*)src_idx)[e];
            if (s < 0) s = 0;
            if (s >= n_nodes) s = n_nodes - 1;
        }
    }
    return s;
}

__global__ void __launch_bounds__(THREADS, 1)
atom2bond_kernel(const float* __restrict__ atom,
                 const float* __restrict__ edge,
                 const void*  __restrict__ src_idx,
                 const float* __restrict__ Wg,
                 const float* __restrict__ bg,
                 float* __restrict__ out,
                 int E, int ntiles, long n_nodes, int use_rounded) {
    extern __shared__ char sm[];
    const uint32_t smb  = smem_u32(sm);
    const uint32_t mbar = smb + OFF_MBAR;
    float* Wf = (float*)(sm + OFF_WF);
    float* As = (float*)(sm + OFF_AS);

    const int tid  = threadIdx.x;
    const int lane = tid & 31;
    const int warp = tid >> 5;
    const int g  = lane >> 2;
    const int t  = lane & 3;
    const int wm = warp >> 1;             // 0..3 row block (32 edges)
    const int wn = warp & 1;              // 0..1 col half (64 outputs)
    const int is64 = g_idx_is64;
    const float* asrc = use_rounded ? g_atom_r : atom;

    if (tid == 0) MBAR_INIT(mbar, THREADS);
    __syncthreads();

    // ---- prologue: start tile-0 loads immediately ----
    long tile = blockIdx.x;
    long s_cur = idx_ld(tile, src_idx, is64, E, n_nodes);
    float4 ev[8];
    edge_ldg(ev, tile, edge, E);
    atom_issue(smb + OFF_AS, mbar, tile, s_cur, asrc, E);     // overlaps W build below
    edge_sts(ev, As, (int)(((long)E - tile * BM) * (EDIM / 4) < 2048 ?
                            ((long)E - tile * BM) * (EDIM / 4) : 2048));

    // ---- build W fragments (per-lane contiguous, stride 20 words) + bias regs ----
    // Wf[((wn*NKK+kk)*32 + lane)*20 + (j*2+h)] = tf32( W[kk*8 + t + 4h][wn*64 + j*8 + g] )
    for (int idx = tid; idx < 2 * NKK * 32 * 16; idx += THREADS) {
        const int v  = idx & 15;          // j*2+h
        const int l  = (idx >> 4) & 31;
        const int rk = idx >> 9;          // 0..47
        const int kk = rk % NKK;
        const int wq = rk / NKK;
        const int j  = v >> 1;
        const int h  = v & 1;
        const int krow = kk * 8 + (l & 3) + h * 4;
        const int ncol = wq * 64 + j * 8 + (l >> 2);
        Wf[((wq * NKK + kk) * 32 + l) * 20 + v] =
            __uint_as_float(f32_to_tf32(Wg[krow * NDIM + ncol]));
    }
    float bb[16];
    #pragma unroll
    for (int j = 0; j < 8; j++) {
        bb[j * 2 + 0] = bg[wn * 64 + j * 8 + 2 * t + 0];
        bb[j * 2 + 1] = bg[wn * 64 + j * 8 + 2 * t + 1];
    }
    __syncthreads();                       // Wf + edge STS visible

    const float* Abase = As + (wm * 32 + g) * AS_STRIDE + t;
    const float* Wbase = Wf + (wn * NKK * 32 + lane) * 20;

    uint32_t ph = 0;
    for (;;) {
        MBAR_WAIT(mbar, ph);               // atom rows of `tile` landed (acquire)
        ph ^= 1;

        const long tn = tile + gridDim.x;
        const bool more = (tn < (long)ntiles);
        long s_nxt = 0;
        if (more) {
            s_nxt = idx_ld(tn, src_idx, is64, E, n_nodes);
            edge_ldg(ev, tn, edge, E);     // latency hidden under MMA
        }

        // ---- MMA: warp = 32 edges x 64 outputs, K=192 ----
        float acc[2][8][4];
        #pragma unroll
        for (int i = 0; i < 2; i++)
            #pragma unroll
            for (int j = 0; j < 8; j++)
                #pragma unroll
                for (int c = 0; c < 4; c++) acc[i][j][c] = 0.f;

        #pragma unroll
        for (int kk = 0; kk < NKK; kk++) {
            uint32_t a[2][4];
            #pragma unroll
            for (int i = 0; i < 2; i++) {
                const float* Ar = Abase + i * 16 * AS_STRIDE + kk * 8;
                a[i][0] = __float_as_uint(Ar[0]);
                a[i][1] = __float_as_uint(Ar[8 * AS_STRIDE]);
                a[i][2] = __float_as_uint(Ar[4]);
                a[i][3] = __float_as_uint(Ar[8 * AS_STRIDE + 4]);
            }
            const float* Wr = Wbase + kk * 640;
            const float4 q0 = *(const float4*)(Wr + 0);
            const float4 q1 = *(const float4*)(Wr + 4);
            const float4 q2 = *(const float4*)(Wr + 8);
            const float4 q3 = *(const float4*)(Wr + 12);
            uint32_t b[16];
            b[0]=__float_as_uint(q0.x);  b[1]=__float_as_uint(q0.y);
            b[2]=__float_as_uint(q0.z);  b[3]=__float_as_uint(q0.w);
            b[4]=__float_as_uint(q1.x);  b[5]=__float_as_uint(q1.y);
            b[6]=__float_as_uint(q1.z);  b[7]=__float_as_uint(q1.w);
            b[8]=__float_as_uint(q2.x);  b[9]=__float_as_uint(q2.y);
            b[10]=__float_as_uint(q2.z); b[11]=__float_as_uint(q2.w);
            b[12]=__float_as_uint(q3.x); b[13]=__float_as_uint(q3.y);
            b[14]=__float_as_uint(q3.z); b[15]=__float_as_uint(q3.w);
            #pragma unroll
            for (int i = 0; i < 2; i++)
                #pragma unroll
                for (int j = 0; j < 8; j++)
                    mma_tf32(acc[i][j], a[i], b + 2 * j);
        }

        __syncthreads();                   // all warps done reading As(tile)

        if (more) {
            const long vr = (long)E - tn * BM;
            const int vf4 = (int)((vr * (EDIM / 4) < 2048) ? vr * (EDIM / 4) : 2048);
            edge_sts(ev, As, vf4);                      // STS before arrive (release)
            atom_issue(smb + OFF_AS, mbar, tn, s_nxt, asrc, E);
        }

        // ---- epilogue(tile): bias + relu + STG (overlaps in-flight copies) ----
        const long eb = tile * (long)BM;
        #pragma unroll
        for (int i = 0; i < 2; i++) {
            #pragma unroll
            for (int rr = 0; rr < 2; rr++) {
                const long e = eb + wm * 32 + i * 16 + rr * 8 + g;
                if (e < (long)E) {
                    float* orow = out + e * (long)NDIM;
                    #pragma unroll
                    for (int j = 0; j < 8; j++) {
                        const int c = wn * 64 + j * 8 + 2 * t;
                        float v0 = fmaxf(acc[i][j][rr * 2 + 0] + bb[j * 2 + 0], 0.f);
                        float v1 = fmaxf(acc[i][j][rr * 2 + 1] + bb[j * 2 + 1], 0.f);
                        *(float2*)(orow + c) = make_float2(v0, v1);
                    }
                }
            }
        }

        if (!more) break;
        tile = tn;
    }
}

extern "C" void kernel_launch(void* const* d_in, const int* in_sizes, int n_in,
                              void* d_out, int out_size) {
    const float* atom = (const float*)d_in[0];   // [N_NODES,128] f32
    const float* edge = (const float*)d_in[1];   // [E,64] f32
    const void*  src  = d_in[2];                 // [E] int32 or int64 (detected)
    const float* W    = (const float*)d_in[3];   // [192,128] f32
    const float* b    = (const float*)d_in[4];   // [128] f32
    float* out = (float*)d_out;                  // [E,128] f32

    const int  E       = in_sizes[2];
    const long n_atomf = (long)in_sizes[0];
    const long n_nodes = n_atomf / NDIM;
    const int  ntiles  = (E + BM - 1) / BM;
    const int  use_rounded = (n_nodes <= ATOM_CAP_ROWS) ? 1 : 0;

    int n_words = E < 2048 ? E : 2048;
    detect_idx_dtype_kernel<<<1, 1>>>((const int*)src, n_words);
    if (use_rounded)
        round_atom_kernel<<<148, 256>>>(atom, n_atomf);

    cudaFuncSetAttribute(atom2bond_kernel,
                         cudaFuncAttributeMaxDynamicSharedMemorySize, SMEM_TOTAL);

    int grid = ntiles < 148 ? ntiles : 148;
    atom2bond_kernel<<<grid, THREADS, SMEM_TOTAL>>>(atom, edge, src, W, b, out,
                                                    E, ntiles, n_nodes, use_rounded);
}

// round 7
// speedup vs baseline: 3.7693x; 1.5974x over previous
#include <cuda_runtime.h>
#include <cuda_fp16.h>
#include <cstdint>

#define NDIM    128
#define EDIM    64
#define KDIM    192
#define BM      128
#define THREADS 256
#define NKK     12                        // K steps of 16 (fp16 mma)

#define AS_WROW 100                       // A row stride in 32-bit words (200 halves, 400B)
#define AS_BUF_BYTES (BM * AS_WROW * 4)   // 51200 B per buffer
#define WF_WORDS (2 * NKK * 32 * 20)      // 15360 words (16 used + 4 pad per lane-kk)

#define OFF_MBAR 0                        // two mbarriers @0, @8
#define OFF_WF   1024
#define OFF_AS   (OFF_WF + WF_WORDS * 4)  // 62464
#define SMEM_TOTAL (OFF_AS + 2 * AS_BUF_BYTES)   // 164864 B

#define ATOM_CAP_ROWS 16384
__device__ __half g_atom_h[ATOM_CAP_ROWS * NDIM];   // fp16 pre-converted atom table
__device__ int    g_idx_is64;

__global__ void detect_idx_dtype_kernel(const int* __restrict__ buf, int n_words) {
    __shared__ int nz;
    if (threadIdx.x == 0) nz = 0;
    __syncthreads();
    int local = 0;
    for (int i = 1 + 2 * threadIdx.x; i < n_words; i += 2 * blockDim.x)
        local += (buf[i] != 0);
    if (local) atomicAdd(&nz, 1);
    __syncthreads();
    if (threadIdx.x == 0) g_idx_is64 = (nz == 0) ? 1 : 0;
}

__global__ void cvt_atom_kernel(const float* __restrict__ a, long n) {
    for (long i = blockIdx.x * (long)blockDim.x + threadIdx.x; i < n;
         i += (long)gridDim.x * blockDim.x)
        g_atom_h[i] = __float2half_rn(a[i]);
}

__device__ __forceinline__ void mma_f16(float d[4], const uint32_t a[4], const uint32_t b[2]) {
    asm volatile(
        "mma.sync.aligned.m16n8k16.row.col.f32.f16.f16.f32 "
        "{%0,%1,%2,%3}, {%4,%5,%6,%7}, {%8,%9}, {%0,%1,%2,%3};\n"
        : "+f"(d[0]), "+f"(d[1]), "+f"(d[2]), "+f"(d[3])
        : "r"(a[0]), "r"(a[1]), "r"(a[2]), "r"(a[3]),
          "r"(b[0]), "r"(b[1]));
}

__device__ __forceinline__ uint32_t smem_u32(const void* p) {
    uint32_t a;
    asm("{ .reg .u64 t; cvta.to.shared.u64 t, %1; cvt.u32.u64 %0, t; }" : "=r"(a) : "l"(p));
    return a;
}
__device__ __forceinline__ uint32_t pack_h2(float x, float y) {
    __half2 h = __floats2half2_rn(x, y);
    return *(uint32_t*)&h;
}

#define MBAR_INIT(mb, c) \
    asm volatile("mbarrier.init.shared.b64 [%0], %1;" :: "r"(mb), "r"((uint32_t)(c)) : "memory")
#define MBAR_ARRIVE(mb) \
    asm volatile("mbarrier.arrive.shared::cta.b64 _, [%0];" :: "r"(mb) : "memory")
#define MBAR_ARRIVE_TX(mb, tx) \
    asm volatile("mbarrier.arrive.expect_tx.shared::cta.b64 _, [%0], %1;" \
                 :: "r"(mb), "r"((uint32_t)(tx)) : "memory")
#define MBAR_WAIT(mb, ph) do { \
    asm volatile("{\n\t.reg .pred P1;\n\t" \
        "WL_%=:\n\t" \
        "mbarrier.try_wait.parity.acquire.cta.shared::cta.b64 P1, [%0], %1, 0x989680;\n\t" \
        "@P1 bra.uni WD_%=;\n\t" \
        "bra.uni WL_%=;\n\t" \
        "WD_%=:\n\t}" :: "r"(mb), "r"((uint32_t)(ph)) : "memory"); \
} while (0)
#define BULK_CP(dst, src, bytes, mb) \
    asm volatile("cp.async.bulk.shared::cta.global.mbarrier::complete_tx::bytes [%0], [%1], %2, [%3];" \
                 :: "r"(dst), "l"(src), "r"((uint32_t)(bytes)), "r"(mb) : "memory")

// ---- edge staging ----
__device__ __forceinline__ void edge_ldg(float4 ev[8], long tile,
                                         const float* __restrict__ edge, int E) {
    const int tid = threadIdx.x;
    const long eb = tile * (long)BM;
    const long vr = (long)E - eb;
    const int vf4 = (int)((vr * (EDIM / 4) < 2048) ? vr * (EDIM / 4) : 2048);
    const float4* base = (const float4*)(edge + eb * EDIM);
    #pragma unroll
    for (int u = 0; u < 8; u++) {
        const int f4 = u * THREADS + tid;
        ev[u] = (f4 < vf4) ? __ldg(base + f4) : make_float4(0.f, 0.f, 0.f, 0.f);
    }
}
__device__ __forceinline__ void edge_sts(const float4 ev[8], uint32_t* __restrict__ As32,
                                         long tile, int E) {
    const int tid = threadIdx.x;
    const long vr = (long)E - tile * (long)BM;
    const int vf4 = (int)((vr * (EDIM / 4) < 2048) ? vr * (EDIM / 4) : 2048);
    #pragma unroll
    for (int u = 0; u < 8; u++) {
        const int f4 = u * THREADS + tid;
        if (f4 < vf4) {
            const int r = f4 >> 4;
            uint32_t* dst = As32 + r * AS_WROW + 64 + (f4 & 15) * 2;
            dst[0] = pack_h2(ev[u].x, ev[u].y);
            dst[1] = pack_h2(ev[u].z, ev[u].w);
        }
    }
}

__device__ __forceinline__ long idx_ld(long tile, const void* __restrict__ src_idx,
                                       int is64, int E, long n_nodes) {
    const int tid = threadIdx.x;
    long s = 0;
    if (tid < BM) {
        const long e = tile * (long)BM + tid;
        if (e < (long)E) {
            s = is64 ? (long)((const long long*)src_idx)[e]
                     : (long)((const int*)src_idx)[e];
            if (s < 0) s = 0;
            if (s >= n_nodes) s = n_nodes - 1;
        }
    }
    return s;
}

// ---- atom rows: bulk copy (fast path) ----
__device__ __forceinline__ void atom_issue(uint32_t as_smem, uint32_t mbar, long tile,
                                           long s, int E) {
    const int tid = threadIdx.x;
    if (tid < BM && (tile * (long)BM + tid) < (long)E) {
        MBAR_ARRIVE_TX(mbar, NDIM * 2);
        BULK_CP(as_smem + (uint32_t)(tid * AS_WROW * 4),
                (const void*)(g_atom_h + s * (long)NDIM), NDIM * 2, mbar);
    } else {
        MBAR_ARRIVE(mbar);
    }
}
// ---- atom rows: LDG fallback (n_nodes > cap), 2 threads/row ----
__device__ __forceinline__ void atom_fallback(uint32_t* __restrict__ As32, long tile,
                                              const float* __restrict__ atom,
                                              const void* __restrict__ src_idx,
                                              int is64, int E, long n_nodes) {
    const int tid  = threadIdx.x;
    const int r    = tid >> 1;
    const int half = tid & 1;
    const long e   = tile * (long)BM + r;
    if (e >= (long)E) return;
    long s = is64 ? (long)((const long long*)src_idx)[e]
                  : (long)((const int*)src_idx)[e];
    if (s < 0) s = 0;
    if (s >= n_nodes) s = n_nodes - 1;
    const float4* arow = (const float4*)(atom + s * (long)NDIM) + half * 16;
    uint32_t* dst = As32 + r * AS_WROW + half * 32;
    #pragma unroll
    for (int u = 0; u < 16; u++) {
        float4 v = __ldg(arow + u);
        dst[u * 2 + 0] = pack_h2(v.x, v.y);
        dst[u * 2 + 1] = pack_h2(v.z, v.w);
    }
}

__global__ void __launch_bounds__(THREADS, 1)
atom2bond_kernel(const float* __restrict__ atom,
                 const float* __restrict__ edge,
                 const void*  __restrict__ src_idx,
                 const float* __restrict__ Wg,
                 const float* __restrict__ bg,
                 float* __restrict__ out,
                 int E, int ntiles, long n_nodes, int fast) {
    extern __shared__ char sm[];
    const uint32_t smb = smem_u32(sm);
    uint32_t* Wf = (uint32_t*)(sm + OFF_WF);

    const int tid  = threadIdx.x;
    const int lane = tid & 31;
    const int warp = tid >> 5;
    const int g  = lane >> 2;
    const int t  = lane & 3;
    const int wm = warp >> 1;
    const int wn = warp & 1;
    const int is64 = g_idx_is64;

    if (tid == 0) { MBAR_INIT(smb + OFF_MBAR, THREADS); MBAR_INIT(smb + OFF_MBAR + 8, THREADS); }
    __syncthreads();

    // ---- prologue: tile 0 into buffer 0 ----
    long tile = blockIdx.x;
    uint32_t* As0 = (uint32_t*)(sm + OFF_AS);
    if (fast) {
        long s0 = idx_ld(tile, src_idx, is64, E, n_nodes);
        atom_issue(smb + OFF_AS, smb + OFF_MBAR, tile, s0, E);
    } else {
        atom_fallback(As0, tile, atom, src_idx, is64, E, n_nodes);
        MBAR_ARRIVE(smb + OFF_MBAR);
    }
    float4 ev[8];
    edge_ldg(ev, tile, edge, E);
    edge_sts(ev, As0, tile, E);

    // ---- W fragments (fp16 half2 words, per-lane contiguous stride 20) ----
    // Wf[((wq*NKK+kk)*32 + l)*20 + (j*2+h)] = half2( W[kk*16+h*8+2t][n], W[..+1][n] ), n=wq*64+j*8+g
    for (int idx = tid; idx < 2 * NKK * 32 * 16; idx += THREADS) {
        const int v  = idx & 15;
        const int l  = (idx >> 4) & 31;
        const int rk = idx >> 9;
        const int kk = rk % NKK;
        const int wq = rk / NKK;
        const int j  = v >> 1;
        const int h  = v & 1;
        const int k  = kk * 16 + h * 8 + 2 * (l & 3);
        const int n  = wq * 64 + j * 8 + (l >> 2);
        Wf[((wq * NKK + kk) * 32 + l) * 20 + v] =
            pack_h2(Wg[k * NDIM + n], Wg[(k + 1) * NDIM + n]);
    }
    float bb[16];
    #pragma unroll
    for (int j = 0; j < 8; j++) {
        bb[j * 2 + 0] = bg[wn * 64 + j * 8 + 2 * t + 0];
        bb[j * 2 + 1] = bg[wn * 64 + j * 8 + 2 * t + 1];
    }
    __syncthreads();

    const uint32_t* Wbase = Wf + (wn * NKK * 32 + lane) * 20;

    uint32_t ph[2] = {0, 0};
    int bi = 0;
    for (;;) {
        MBAR_WAIT(smb + OFF_MBAR + bi * 8, ph[bi]);      // atoms(tile) landed in buf[bi]
        ph[bi] ^= 1;

        const long tn = tile + gridDim.x;
        const bool more = (tn < (long)ntiles);
        const int  bn = bi ^ 1;
        uint32_t* Ascur = (uint32_t*)(sm + OFF_AS + bi * AS_BUF_BYTES);
        uint32_t* Asnxt = (uint32_t*)(sm + OFF_AS + bn * AS_BUF_BYTES);

        // issue next tile's atoms + edge LDGs BEFORE the MMA — full overlap
        if (more) {
            if (fast) {
                long sn = idx_ld(tn, src_idx, is64, E, n_nodes);
                atom_issue(smb + OFF_AS + bn * AS_BUF_BYTES, smb + OFF_MBAR + bn * 8, tn, sn, E);
            }
            edge_ldg(ev, tn, edge, E);
        }

        // ---- MMA: warp = 32 edges x 64 outputs, K=192, fp16 k16 steps ----
        float acc[2][8][4];
        #pragma unroll
        for (int i = 0; i < 2; i++)
            #pragma unroll
            for (int j = 0; j < 8; j++)
                #pragma unroll
                for (int c = 0; c < 4; c++) acc[i][j][c] = 0.f;

        const uint32_t* Ab = Ascur + (wm * 32 + g) * AS_WROW + t;
        #pragma unroll
        for (int kk = 0; kk < NKK; kk++) {
            uint32_t a[2][4];
            #pragma unroll
            for (int i = 0; i < 2; i++) {
                const uint32_t* Ar = Ab + i * 16 * AS_WROW + kk * 8;
                a[i][0] = Ar[0];
                a[i][1] = Ar[8 * AS_WROW];
                a[i][2] = Ar[4];
                a[i][3] = Ar[8 * AS_WROW + 4];
            }
            const uint32_t* Wr = Wbase + kk * 640;
            uint4 q0 = *(const uint4*)(Wr + 0);
            uint4 q1 = *(const uint4*)(Wr + 4);
            uint4 q2 = *(const uint4*)(Wr + 8);
            uint4 q3 = *(const uint4*)(Wr + 12);
            uint32_t b[16] = {q0.x,q0.y,q0.z,q0.w, q1.x,q1.y,q1.z,q1.w,
                              q2.x,q2.y,q2.z,q2.w, q3.x,q3.y,q3.z,q3.w};
            #pragma unroll
            for (int i = 0; i < 2; i++)
                #pragma unroll
                for (int j = 0; j < 8; j++)
                    mma_f16(acc[i][j], a[i], b + 2 * j);
        }

        // stage next tile's edges (and fallback atoms) into buf[bn]
        if (more) {
            edge_sts(ev, Asnxt, tn, E);
            if (!fast) {
                atom_fallback(Asnxt, tn, atom, src_idx, is64, E, n_nodes);
                MBAR_ARRIVE(smb + OFF_MBAR + bn * 8);
            }
        }
        __syncthreads();   // buf[bi] fully read by all warps; buf[bn] edges visible

        // ---- epilogue(tile) ----
        const long eb = tile * (long)BM;
        #pragma unroll
        for (int i = 0; i < 2; i++) {
            #pragma unroll
            for (int rr = 0; rr < 2; rr++) {
                const long e = eb + wm * 32 + i * 16 + rr * 8 + g;
                if (e < (long)E) {
                    float* orow = out + e * (long)NDIM;
                    #pragma unroll
                    for (int j = 0; j < 8; j++) {
                        const int c = wn * 64 + j * 8 + 2 * t;
                        float v0 = fmaxf(acc[i][j][rr * 2 + 0] + bb[j * 2 + 0], 0.f);
                        float v1 = fmaxf(acc[i][j][rr * 2 + 1] + bb[j * 2 + 1], 0.f);
                        *(float2*)(orow + c) = make_float2(v0, v1);
                    }
                }
            }
        }

        if (!more) break;
        tile = tn;
        bi = bn;
    }
}

extern "C" void kernel_launch(void* const* d_in, const int* in_sizes, int n_in,
                              void* d_out, int out_size) {
    const float* atom = (const float*)d_in[0];   // [N_NODES,128] f32
    const float* edge = (const float*)d_in[1];   // [E,64] f32
    const void*  src  = d_in[2];                 // [E] int32 or int64 (detected)
    const float* W    = (const float*)d_in[3];   // [192,128] f32
    const float* b    = (const float*)d_in[4];   // [128] f32
    float* out = (float*)d_out;                  // [E,128] f32

    const int  E       = in_sizes[2];
    const long n_atomf = (long)in_sizes[0];
    const long n_nodes = n_atomf / NDIM;
    const int  ntiles  = (E + BM - 1) / BM;
    const int  fast    = (n_nodes <= ATOM_CAP_ROWS) ? 1 : 0;

    int n_words = E < 4096 ? E : 4096;
    detect_idx_dtype_kernel<<<1, 256>>>((const int*)src, n_words);
    if (fast)
        cvt_atom_kernel<<<148, 256>>>(atom, n_atomf);

    cudaFuncSetAttribute(atom2bond_kernel,
                         cudaFuncAttributeMaxDynamicSharedMemorySize, SMEM_TOTAL);

    int grid = ntiles < 148 ? ntiles : 148;
    atom2bond_kernel<<<grid, THREADS, SMEM_TOTAL>>>(atom, edge, src, W, b, out,
                                                    E, ntiles, n_nodes, fast);
}